// round 4
// baseline (speedup 1.0000x reference)
#include <cuda_runtime.h>
#include <cstddef>
#include <cstdint>

// Problem constants
#define BB   128     // batch
#define TT   512     // seq len
#define EE   256     // embed dim
#define HH   256     // hidden
#define G4H  1024    // 4*H
#define VV   32000   // vocab
#define NC   32      // classes

// ---------------- device scratch (no allocations allowed) ----------------
__device__ float g_P[(size_t)VV * 2048];     // [V][2*4H]  vocab projection (+bias folded)
__device__ float g_hfinT[2][HH][BB];         // final hidden per direction, transposed

// ---------------- f32x2 helpers (FFMA2 path, PTX-only) ----------------
__device__ __forceinline__ unsigned long long pack2(float lo, float hi) {
    unsigned long long r;
    asm("mov.b64 %0, {%1, %2};" : "=l"(r) : "f"(lo), "f"(hi));
    return r;
}
__device__ __forceinline__ float2 unpack2(unsigned long long v) {
    float2 r;
    asm("mov.b64 {%0, %1}, %2;" : "=f"(r.x), "=f"(r.y) : "l"(v));
    return r;
}
__device__ __forceinline__ void ffma2(unsigned long long& d, unsigned long long a, unsigned long long b) {
    asm("fma.rn.f32x2 %0, %1, %2, %0;" : "+l"(d) : "l"(a), "l"(b));
}

__device__ __forceinline__ float sigm(float x) { return 1.0f / (1.0f + expf(-x)); }

// ---------------- cluster / DSMEM helpers ----------------
__device__ __forceinline__ uint32_t mapa_shared(uint32_t addr, uint32_t rank) {
    uint32_t r;
    asm("mapa.shared::cluster.u32 %0, %1, %2;" : "=r"(r) : "r"(addr), "r"(rank));
    return r;
}
__device__ __forceinline__ void st_cluster_v2(uint32_t addr, float x, float y) {
    asm volatile("st.shared::cluster.v2.f32 [%0], {%1, %2};"
                 :: "r"(addr), "f"(x), "f"(y) : "memory");
}
__device__ __forceinline__ void cluster_sync() {
    asm volatile("barrier.cluster.arrive.aligned;" ::: "memory");
    asm volatile("barrier.cluster.wait.aligned;" ::: "memory");
}

// =====================================================================
// Kernel A: P[v, d*1024+g] = sum_e emb[v,e] * W{f,b}[e,g] + b{f,b}[g]
// (unchanged — measured 870us; optimize in a later round)
// =====================================================================
__global__ void __launch_bounds__(256) proj_kernel(
    const float* __restrict__ emb,
    const float* __restrict__ Wf, const float* __restrict__ bf,
    const float* __restrict__ Wb, const float* __restrict__ bb)
{
    __shared__ float As[16][68];
    __shared__ float Bs[16][64];

    const int tid = threadIdx.x;
    const int tx = tid & 15, ty = tid >> 4;
    const int m0 = ty * 4, n0 = tx * 4;
    const int vbase = blockIdx.y * 64;
    const int nbase = blockIdx.x * 64;
    const int d = nbase >> 10;
    const float* W    = d ? Wb : Wf;
    const float* bias = d ? bb : bf;
    const int gbase = nbase & 1023;

    unsigned long long acc[4][2] = {};

    for (int kt = 0; kt < 256; kt += 16) {
        #pragma unroll
        for (int i = tid; i < 1024; i += 256) {
            int row = i >> 4, k = i & 15;
            As[k][row] = emb[(size_t)(vbase + row) * EE + kt + k];
        }
        #pragma unroll
        for (int i = tid; i < 1024; i += 256) {
            int k = i >> 6, c = i & 63;
            Bs[k][c] = W[(size_t)(kt + k) * G4H + gbase + c];
        }
        __syncthreads();
        #pragma unroll
        for (int k = 0; k < 16; k++) {
            float4 a4 = *(const float4*)&As[k][m0];
            const unsigned long long* bp = (const unsigned long long*)&Bs[k][n0];
            unsigned long long b0 = bp[0], b1 = bp[1];
            #pragma unroll
            for (int i = 0; i < 4; i++) {
                float av = ((const float*)&a4)[i];
                unsigned long long ad = pack2(av, av);
                ffma2(acc[i][0], ad, b0);
                ffma2(acc[i][1], ad, b1);
            }
        }
        __syncthreads();
    }

    #pragma unroll
    for (int i = 0; i < 4; i++) {
        int v = vbase + m0 + i;
        #pragma unroll
        for (int p = 0; p < 2; p++) {
            float2 va = unpack2(acc[i][p]);
            int c = n0 + 2 * p;
            va.x += bias[gbase + c];
            va.y += bias[gbase + c + 1];
            *(float2*)&g_P[(size_t)v * 2048 + nbase + c] = va;
        }
    }
}

// =====================================================================
// Kernel B: batch-partitioned bidirectional LSTM with 8-CTA clusters.
//
// Cluster = (direction d, row block of 16 batch rows). 16 clusters total.
// CTA rank c of a cluster owns h-cols [c*32, c*32+32) -> 128 z-cols
// {g*256 + c*32 + m}. Its U slice (256 x 128 fp32 = 128 KB, gate-major
// rearranged) is SMEM-resident for the whole kernel.
// The 16x256 h block is double-buffered in every CTA's SMEM; each step every
// CTA pushes its freshly computed h slice (16 rows x 32 cols) to all 8
// cluster CTAs via DSMEM remote stores, then one cluster.sync.
// No global h traffic. No global barrier. All fp32.
//
// Thread map: cg = tid&15 (8 z-cols = 2 hcols x 4 gates), lrow = tid>>4.
// f32x2 packed over the hcol pair -> 4 accumulators (one per gate).
// =====================================================================
#define US_FLOATS   (256 * 128)             // 128 KB
#define HS_FLOATS   (16 * 256)              // 16 KB per buffer
#define LSTM_SMEM_BYTES ((US_FLOATS + 2 * HS_FLOATS) * 4)   // 160 KB

__global__ void __launch_bounds__(256) lstm_kernel(
    const int* __restrict__ tokens,
    const float* __restrict__ Uf, const float* __restrict__ Ub)
{
    extern __shared__ float sm[];
    float* Us = sm;                          // [256 k][4 g][32 m]
    float* hs = sm + US_FLOATS;              // [2 buf][16 row][256 k]

    const int tid  = threadIdx.x;
    const int cl   = blockIdx.x >> 3;        // cluster id 0..15
    const int c    = blockIdx.x & 7;         // rank in cluster
    const int d    = cl >> 3;                // 0 fwd, 1 bwd
    const int rb   = (cl & 7) * 16;          // batch row block base
    const float* U = d ? Ub : Uf;

    const int cg   = tid & 15;
    const int lrow = tid >> 4;

    // Token dtype guard (jnp.int64 silently x32 in JAX unless x64 enabled).
    const bool is64 = ((tokens[1] | tokens[3] | tokens[5] | tokens[7]) == 0);
    const int ts = is64 ? 2 : 1;

    // Load U slice, gate-major: Us[k*128 + g*32 + j] = U[k][g*256 + c*32 + j]
    // (coalesced over j)
    for (int i = tid; i < US_FLOATS; i += 256) {
        int k = i >> 7, cc = i & 127;
        int g = cc >> 5, j = cc & 31;
        Us[i] = U[(size_t)k * G4H + g * 256 + c * 32 + j];
    }
    // Zero-init h buffer 0 (local copy)
    for (int i = tid; i < HS_FLOATS; i += 256) hs[i] = 0.f;

    // Remote hs base addresses for all 8 cluster CTAs (incl. self)
    const uint32_t hs_local = (uint32_t)__cvta_generic_to_shared(hs);
    uint32_t rbase[8];
    #pragma unroll
    for (int r = 0; r < 8; r++) rbase[r] = mapa_shared(hs_local, r);

    __syncthreads();
    cluster_sync();   // all SMEM init done; DSMEM targets valid

    const int rowg = rb + lrow;
    const int* myTok = tokens + (size_t)rowg * TT * ts;
    const float* hrow0 = hs + lrow * 256;
    // per-step remote store offset (bytes) within a buffer
    const uint32_t stoff = (uint32_t)((lrow * 256 + c * 32 + 2 * cg) * 4);

    float cs0 = 0.f, cs1 = 0.f;

    for (int t = 0; t < TT; t++) {
        const int buf = t & 1;
        const int te  = d ? (TT - 1 - t) : t;
        int tok = myTok[te * ts];
        tok = (tok >= 0 && tok < VV) ? tok : 0;

        // input projection for this (row, 8 z-cols) — issued early, consumed late
        const float* Pb = g_P + (size_t)tok * 2048 + d * 1024 + c * 32 + 2 * cg;
        float2 p0 = *(const float2*)(Pb);
        float2 p1 = *(const float2*)(Pb + 256);
        float2 p2 = *(const float2*)(Pb + 512);
        float2 p3 = *(const float2*)(Pb + 768);

        // z = h(t-1) . U  over k = 256 (all local SMEM)
        const float* hrow = hrow0 + buf * HS_FLOATS;
        unsigned long long a0 = 0, a1 = 0, a2 = 0, a3 = 0;
        #pragma unroll 8
        for (int k = 0; k < HH; k++) {
            float hv = hrow[k];
            unsigned long long hd = pack2(hv, hv);
            const float* uk = Us + k * 128 + 2 * cg;
            ffma2(a0, hd, *(const unsigned long long*)(uk));
            ffma2(a1, hd, *(const unsigned long long*)(uk + 32));
            ffma2(a2, hd, *(const unsigned long long*)(uk + 64));
            ffma2(a3, hd, *(const unsigned long long*)(uk + 96));
        }

        float2 zi = unpack2(a0), zf = unpack2(a1), zg = unpack2(a2), zo = unpack2(a3);
        zi.x += p0.x; zi.y += p0.y;
        zf.x += p1.x; zf.y += p1.y;
        zg.x += p2.x; zg.y += p2.y;
        zo.x += p3.x; zo.y += p3.y;

        float i0 = sigm(zi.x), i1 = sigm(zi.y);
        float f0 = sigm(zf.x), f1 = sigm(zf.y);
        float g0 = tanhf(zg.x), g1 = tanhf(zg.y);
        float o0 = sigm(zo.x), o1 = sigm(zo.y);
        cs0 = f0 * cs0 + i0 * g0;
        cs1 = f1 * cs1 + i1 * g1;
        float h0 = o0 * tanhf(cs0);
        float h1 = o1 * tanhf(cs1);

        if (t == TT - 1) {
            // final h -> global (each CTA owns its 32 hcols: no duplication)
            g_hfinT[d][c * 32 + 2 * cg][rowg]     = h0;
            g_hfinT[d][c * 32 + 2 * cg + 1][rowg] = h1;
        } else {
            // push h slice to all 8 cluster CTAs' next-phase buffer
            const uint32_t off = (uint32_t)((buf ^ 1) * HS_FLOATS * 4) + stoff;
            #pragma unroll
            for (int r = 0; r < 8; r++)
                st_cluster_v2(rbase[r] + off, h0, h1);
            cluster_sync();   // publishes h(t) cluster-wide (DSMEM visibility)
        }
    }
}

// =====================================================================
// Kernel C: head.  h1 = relu([hf|hb] @ W1 + b1); out = softmax(h1 @ W2 + b2)
// =====================================================================
__global__ void __launch_bounds__(256) head_kernel(
    const float* __restrict__ W1, const float* __restrict__ b1,
    const float* __restrict__ W2, const float* __restrict__ b2,
    float* __restrict__ out)
{
    __shared__ float hc[8][512];
    __shared__ float h1[8][256];

    const int tid = threadIdx.x;
    const int rb = blockIdx.x * 8;

    for (int i = tid; i < 4096; i += 256) {
        int rr = i >> 9, k = i & 511;
        int dd = k >> 8, kk = k & 255;
        hc[rr][k] = g_hfinT[dd][kk][rb + rr];
    }
    __syncthreads();

    const int j = tid;
    float acc[8] = {0.f, 0.f, 0.f, 0.f, 0.f, 0.f, 0.f, 0.f};
    for (int k = 0; k < 512; k++) {
        float w = W1[(size_t)k * HH + j];
        #pragma unroll
        for (int rr = 0; rr < 8; rr++) acc[rr] += hc[rr][k] * w;
    }
    float bj = b1[j];
    #pragma unroll
    for (int rr = 0; rr < 8; rr++) h1[rr][j] = fmaxf(acc[rr] + bj, 0.f);
    __syncthreads();

    const int rr = tid >> 5, cc = tid & 31;
    float l = b2[cc];
    for (int k = 0; k < HH; k++) l += h1[rr][k] * W2[(size_t)k * NC + cc];

    float m = l;
    #pragma unroll
    for (int o = 16; o > 0; o >>= 1) m = fmaxf(m, __shfl_xor_sync(0xffffffffu, m, o));
    float e = expf(l - m);
    float ssum = e;
    #pragma unroll
    for (int o = 16; o > 0; o >>= 1) ssum += __shfl_xor_sync(0xffffffffu, ssum, o);
    out[(size_t)(rb + rr) * NC + cc] = e / ssum;
}

// =====================================================================
extern "C" void kernel_launch(void* const* d_in, const int* in_sizes, int n_in,
                              void* d_out, int out_size)
{
    const int*   tokens = (const int*)d_in[0];
    const float* emb = (const float*)d_in[1];
    const float* Wf  = (const float*)d_in[2];
    const float* Uf  = (const float*)d_in[3];
    const float* bf  = (const float*)d_in[4];
    const float* Wb  = (const float*)d_in[5];
    const float* Ub  = (const float*)d_in[6];
    const float* bb  = (const float*)d_in[7];
    const float* W1  = (const float*)d_in[8];
    const float* b1  = (const float*)d_in[9];
    const float* W2  = (const float*)d_in[10];
    const float* b2  = (const float*)d_in[11];
    float* out = (float*)d_out;

    cudaFuncSetAttribute(lstm_kernel, cudaFuncAttributeMaxDynamicSharedMemorySize, LSTM_SMEM_BYTES);

    proj_kernel<<<dim3(32, 500), 256>>>(emb, Wf, bf, Wb, bb);

    // cluster launch: 128 CTAs = 16 independent clusters of 8
    {
        cudaLaunchConfig_t cfg = {};
        cfg.gridDim  = dim3(128, 1, 1);
        cfg.blockDim = dim3(256, 1, 1);
        cfg.dynamicSmemBytes = LSTM_SMEM_BYTES;
        cudaLaunchAttribute attrs[1];
        attrs[0].id = cudaLaunchAttributeClusterDimension;
        attrs[0].val.clusterDim.x = 8;
        attrs[0].val.clusterDim.y = 1;
        attrs[0].val.clusterDim.z = 1;
        cfg.attrs = attrs;
        cfg.numAttrs = 1;
        cudaLaunchKernelEx(&cfg, lstm_kernel, tokens, Uf, Ub);
    }

    head_kernel<<<16, 256>>>(W1, b1, W2, b2, out);
}

// round 6
// speedup vs baseline: 1.0232x; 1.0232x over previous
#include <cuda_runtime.h>
#include <cstddef>
#include <cstdint>

// Problem constants
#define BB   128     // batch
#define TT   512     // seq len
#define EE   256     // embed dim
#define HH   256     // hidden
#define G4H  1024    // 4*H
#define VV   32000   // vocab
#define NC   32      // classes

typedef unsigned long long ull;

// ---------------- device scratch (no allocations allowed) ----------------
__device__ float g_P[(size_t)VV * 2048];       // [V][2*4H] vocab projection
__device__ float g_hx[16][2][16][256];         // [group][buf][row16][col256] h exchange
__device__ float g_hfinT[2][HH][BB];           // final hidden per direction, transposed
__device__ int   g_ctr[16 * 32];               // per-group barrier counters (128B apart)

// ---------------- f32x2 helpers ----------------
__device__ __forceinline__ ull pack2(float lo, float hi) {
    ull r;
    asm("mov.b64 %0, {%1, %2};" : "=l"(r) : "f"(lo), "f"(hi));
    return r;
}
__device__ __forceinline__ float2 unpack2(ull v) {
    float2 r;
    asm("mov.b64 {%0, %1}, %2;" : "=f"(r.x), "=f"(r.y) : "l"(v));
    return r;
}
__device__ __forceinline__ void ffma2(ull& d, ull a, ull b) {
    asm("fma.rn.f32x2 %0, %1, %2, %0;" : "+l"(d) : "l"(a), "l"(b));
}

__device__ __forceinline__ int ld_acq(const int* p) {
    int v;
    asm volatile("ld.acquire.gpu.b32 %0, [%1];" : "=r"(v) : "l"(p));
    return v;
}

__device__ __forceinline__ float sigm(float x) { return 1.0f / (1.0f + expf(-x)); }

__device__ __forceinline__ void cpasync16(uint32_t dst, const void* src) {
    asm volatile("cp.async.cg.shared.global [%0], [%1], 16;" :: "r"(dst), "l"(src) : "memory");
}
__device__ __forceinline__ void cp_commit() {
    asm volatile("cp.async.commit_group;" ::: "memory");
}
template<int N> __device__ __forceinline__ void cp_wait() {
    asm volatile("cp.async.wait_group %0;" :: "n"(N) : "memory");
}

// =====================================================================
// Kernel A: P[v, d*1024+g] = sum_e emb[v,e] * W{f,b}[e,g] + b{f,b}[g]
// A pre-duplicated as f32x2 pairs in SMEM; B read via LDS.128.
// Inner loop: 3 LDS + 8 FFMA2 = 11 instr per k.
// Ad padded to 66 ulls/row: stride 528 B = 33*16 -> every LDS.128 16B-aligned.
// Also resets the 16 group barrier counters for kernel B.
// =====================================================================
__global__ void __launch_bounds__(256) proj_kernel(
    const float* __restrict__ emb,
    const float* __restrict__ Wf, const float* __restrict__ bf,
    const float* __restrict__ Wb, const float* __restrict__ bb)
{
    if (blockIdx.x == 0 && blockIdx.y == 0 && threadIdx.x < 16)
        g_ctr[threadIdx.x * 32] = 0;

    __shared__ ull   Ad[16][66];   // dup'd A; row stride 528 B (16B-aligned rows)
    __shared__ float Bs[16][64];

    const int tid = threadIdx.x;
    const int tx = tid & 15, ty = tid >> 4;
    const int m0 = ty * 4, n0 = tx * 4;
    const int vbase = blockIdx.y * 64;
    const int nbase = blockIdx.x * 64;
    const int d = nbase >> 10;
    const float* W    = d ? Wb : Wf;
    const float* bias = d ? bb : bf;
    const int gbase = nbase & 1023;

    ull acc[4][2] = {};

    for (int kt = 0; kt < 256; kt += 16) {
        #pragma unroll
        for (int i = tid; i < 1024; i += 256) {
            int row = i >> 4, k = i & 15;
            float v = emb[(size_t)(vbase + row) * EE + kt + k];
            Ad[k][row] = pack2(v, v);
        }
        #pragma unroll
        for (int i = tid; i < 1024; i += 256) {
            int k = i >> 6, c = i & 63;
            Bs[k][c] = W[(size_t)(kt + k) * G4H + gbase + c];
        }
        __syncthreads();
        #pragma unroll
        for (int k = 0; k < 16; k++) {
            ulonglong2 a01 = *(const ulonglong2*)&Ad[k][m0];
            ulonglong2 a23 = *(const ulonglong2*)&Ad[k][m0 + 2];
            ulonglong2 bb2 = *(const ulonglong2*)&Bs[k][n0];
            ffma2(acc[0][0], a01.x, bb2.x);
            ffma2(acc[0][1], a01.x, bb2.y);
            ffma2(acc[1][0], a01.y, bb2.x);
            ffma2(acc[1][1], a01.y, bb2.y);
            ffma2(acc[2][0], a23.x, bb2.x);
            ffma2(acc[2][1], a23.x, bb2.y);
            ffma2(acc[3][0], a23.y, bb2.x);
            ffma2(acc[3][1], a23.y, bb2.y);
        }
        __syncthreads();
    }

    #pragma unroll
    for (int i = 0; i < 4; i++) {
        int v = vbase + m0 + i;
        #pragma unroll
        for (int p = 0; p < 2; p++) {
            float2 va = unpack2(acc[i][p]);
            int c = n0 + 2 * p;
            va.x += bias[gbase + c];
            va.y += bias[gbase + c + 1];
            *(float2*)&g_P[(size_t)v * 2048 + nbase + c] = va;
        }
    }
}

// =====================================================================
// Kernel B: batch-partitioned bidirectional LSTM, global-L2 exchange.
//
// Group = (direction d, 16-row batch block); 16 groups x 8 CTAs = 128 CTAs.
// CTA rank c owns h-cols [c*32, c*32+32) -> 128 z-cols; its U slice
// (256k x 128, gate-interleaved f32x2 pairs, 128 KB) is SMEM-resident.
// Per step: k-loop (local SMEM) -> h slice STG to g_hx -> fence ->
// per-group atomic barrier (8 arrivals) -> cp.async 16 KB back into SMEM.
// Thread map: cg = tid&15 (2 h-cols x 4 gates), lrow = tid>>4 (batch row).
// =====================================================================
#define US_ULLS  (256 * 64)                       // 128 KB
#define LSTM_SMEM_BYTES (US_ULLS * 8 + 2 * 16 * 256 * 4)   // 160 KB

__global__ void __launch_bounds__(256) lstm_kernel(
    const int* __restrict__ tokens,
    const float* __restrict__ Uf, const float* __restrict__ Ub)
{
    extern __shared__ ull smu[];
    ull*   Us = smu;                              // [256 k][16 cg][4 g] native pairs
    float* hs = (float*)(smu + US_ULLS);          // [2 buf][16 row][256 col]
    const uint32_t hs_addr = (uint32_t)__cvta_generic_to_shared(hs);

    const int tid = threadIdx.x;
    const int gr  = blockIdx.x >> 3;              // group 0..15
    const int c   = blockIdx.x & 7;               // rank in group
    const int d   = gr >> 3;                      // direction
    const int rb  = (gr & 7) * 16;                // batch row base
    const float* U = d ? Ub : Uf;

    const int cg   = tid & 15;
    const int lrow = tid >> 4;

    // Token dtype guard (jnp.int64 silently x32 in JAX unless x64 enabled).
    const bool is64 = ((tokens[1] | tokens[3] | tokens[5] | tokens[7]) == 0);
    const int ts = is64 ? 2 : 1;

    // Load U slice: Us[(k*16+cgx)*4+g] = (U[k][g*256+c*32+2cgx], ...+1)
    for (int i = tid; i < US_ULLS; i += 256) {
        int cgx = i & 15, g = (i >> 4) & 3, k = i >> 6;
        float2 v = *(const float2*)&U[(size_t)k * G4H + g * 256 + c * 32 + 2 * cgx];
        Us[(k * 16 + cgx) * 4 + g] = pack2(v.x, v.y);
    }
    // zero local h buffer 0 (h(-1) = 0)
    for (int i = tid; i < 16 * 256; i += 256) hs[i] = 0.f;
    __syncthreads();

    const int rowg = rb + lrow;
    const int* myTok = tokens + (size_t)rowg * TT * ts;
    int* ctr = &g_ctr[gr * 32];

    float cs0 = 0.f, cs1 = 0.f;

    for (int t = 0; t < TT; t++) {
        const int buf = t & 1;
        const int te  = d ? (TT - 1 - t) : t;
        int tok = myTok[te * ts];
        tok = (tok >= 0 && tok < VV) ? tok : 0;

        // input projection rows (DRAM/L2; consumed after k-loop)
        const float* Pb = g_P + (size_t)tok * 2048 + d * 1024 + c * 32 + 2 * cg;
        float2 p0 = *(const float2*)(Pb);
        float2 p1 = *(const float2*)(Pb + 256);
        float2 p2 = *(const float2*)(Pb + 512);
        float2 p3 = *(const float2*)(Pb + 768);

        if (t > 0) { cp_wait<0>(); __syncthreads(); }   // h(t-1) staged

        // z = h(t-1) . U over k=256 (all local SMEM); 8 instr/k
        const float* hrow = hs + buf * 4096 + lrow * 256;
        const ull* ub = Us + cg * 4;
        ull a0 = 0, a1 = 0, a2 = 0, a3 = 0;
        #pragma unroll 8
        for (int k = 0; k < HH; k++) {
            float hv = hrow[k];
            ull hd = pack2(hv, hv);
            ulonglong2 u01 = *(const ulonglong2*)(ub + k * 64);
            ulonglong2 u23 = *(const ulonglong2*)(ub + k * 64 + 2);
            ffma2(a0, hd, u01.x);
            ffma2(a1, hd, u01.y);
            ffma2(a2, hd, u23.x);
            ffma2(a3, hd, u23.y);
        }

        float2 zi = unpack2(a0), zf = unpack2(a1), zg = unpack2(a2), zo = unpack2(a3);
        zi.x += p0.x; zi.y += p0.y;
        zf.x += p1.x; zf.y += p1.y;
        zg.x += p2.x; zg.y += p2.y;
        zo.x += p3.x; zo.y += p3.y;

        float i0 = sigm(zi.x), i1 = sigm(zi.y);
        float f0 = sigm(zf.x), f1 = sigm(zf.y);
        float g0 = tanhf(zg.x), g1 = tanhf(zg.y);
        float o0 = sigm(zo.x), o1 = sigm(zo.y);
        cs0 = f0 * cs0 + i0 * g0;
        cs1 = f1 * cs1 + i1 * g1;
        float h0 = o0 * tanhf(cs0);
        float h1 = o1 * tanhf(cs1);

        if (t == TT - 1) {
            g_hfinT[d][c * 32 + 2 * cg][rowg]     = h0;
            g_hfinT[d][c * 32 + 2 * cg + 1][rowg] = h1;
        } else {
            const int nb = buf ^ 1;
            // publish h slice
            *(float2*)&g_hx[gr][nb][lrow][c * 32 + 2 * cg] = make_float2(h0, h1);
            __threadfence();
            __syncthreads();
            if (tid == 0) {
                atomicAdd(ctr, 1);
                const int target = 8 * (t + 1);
                while (ld_acq(ctr) < target) { }
            }
            __syncthreads();
            // stage full group h(t) (16 KB) into SMEM, L1-bypassing
            const float4* src = (const float4*)&g_hx[gr][nb][0][0];
            #pragma unroll
            for (int j = 0; j < 4; j++) {
                int f = tid + j * 256;
                cpasync16(hs_addr + (uint32_t)(nb * 4096 + f * 4) * 4, src + f);
            }
            cp_commit();
        }
    }
}

// =====================================================================
// Kernel C: head.  h1 = relu([hf|hb] @ W1 + b1); out = softmax(h1 @ W2 + b2)
// =====================================================================
__global__ void __launch_bounds__(256) head_kernel(
    const float* __restrict__ W1, const float* __restrict__ b1,
    const float* __restrict__ W2, const float* __restrict__ b2,
    float* __restrict__ out)
{
    __shared__ float hc[8][512];
    __shared__ float h1[8][256];

    const int tid = threadIdx.x;
    const int rb = blockIdx.x * 8;

    for (int i = tid; i < 4096; i += 256) {
        int rr = i >> 9, k = i & 511;
        int dd = k >> 8, kk = k & 255;
        hc[rr][k] = g_hfinT[dd][kk][rb + rr];
    }
    __syncthreads();

    const int j = tid;
    float acc[8] = {0.f, 0.f, 0.f, 0.f, 0.f, 0.f, 0.f, 0.f};
    for (int k = 0; k < 512; k++) {
        float w = W1[(size_t)k * HH + j];
        #pragma unroll
        for (int rr = 0; rr < 8; rr++) acc[rr] += hc[rr][k] * w;
    }
    float bj = b1[j];
    #pragma unroll
    for (int rr = 0; rr < 8; rr++) h1[rr][j] = fmaxf(acc[rr] + bj, 0.f);
    __syncthreads();

    const int rr = tid >> 5, cc = tid & 31;
    float l = b2[cc];
    for (int k = 0; k < HH; k++) l += h1[rr][k] * W2[(size_t)k * NC + cc];

    float m = l;
    #pragma unroll
    for (int o = 16; o > 0; o >>= 1) m = fmaxf(m, __shfl_xor_sync(0xffffffffu, m, o));
    float e = expf(l - m);
    float ssum = e;
    #pragma unroll
    for (int o = 16; o > 0; o >>= 1) ssum += __shfl_xor_sync(0xffffffffu, ssum, o);
    out[(size_t)(rb + rr) * NC + cc] = e / ssum;
}

// =====================================================================
extern "C" void kernel_launch(void* const* d_in, const int* in_sizes, int n_in,
                              void* d_out, int out_size)
{
    const int*   tokens = (const int*)d_in[0];
    const float* emb = (const float*)d_in[1];
    const float* Wf  = (const float*)d_in[2];
    const float* Uf  = (const float*)d_in[3];
    const float* bf  = (const float*)d_in[4];
    const float* Wb  = (const float*)d_in[5];
    const float* Ub  = (const float*)d_in[6];
    const float* bb  = (const float*)d_in[7];
    const float* W1  = (const float*)d_in[8];
    const float* b1  = (const float*)d_in[9];
    const float* W2  = (const float*)d_in[10];
    const float* b2  = (const float*)d_in[11];
    float* out = (float*)d_out;

    cudaFuncSetAttribute(lstm_kernel, cudaFuncAttributeMaxDynamicSharedMemorySize, LSTM_SMEM_BYTES);

    proj_kernel<<<dim3(32, 500), 256>>>(emb, Wf, bf, Wb, bb);
    lstm_kernel<<<128, 256, LSTM_SMEM_BYTES>>>(tokens, Uf, Ub);
    head_kernel<<<16, 256>>>(W1, b1, W2, b2, out);
}

// round 7
// speedup vs baseline: 1.9447x; 1.9006x over previous
#include <cuda_runtime.h>
#include <cstddef>
#include <cstdint>

// Problem constants
#define BB   128     // batch
#define TT   512     // seq len
#define EE   256     // embed dim
#define HH   256     // hidden
#define G4H  1024    // 4*H
#define VV   32000   // vocab
#define NC   32      // classes

typedef unsigned long long ull;

// ---------------- device scratch (no allocations allowed) ----------------
__device__ float g_P[(size_t)VV * 2048];       // [V][2*4H] vocab projection
__device__ ull   g_hxd[16][2][HH][16];         // [group][buf][hcol][row] DUPLICATED h pairs
__device__ float g_hfinT[2][HH][BB];           // final hidden per direction, transposed
__device__ int   g_ctr[16 * 32];               // per-group barrier counters (128B apart)

// ---------------- f32x2 helpers ----------------
__device__ __forceinline__ ull pack2(float lo, float hi) {
    ull r;
    asm("mov.b64 %0, {%1, %2};" : "=l"(r) : "f"(lo), "f"(hi));
    return r;
}
__device__ __forceinline__ float2 unpack2(ull v) {
    float2 r;
    asm("mov.b64 {%0, %1}, %2;" : "=f"(r.x), "=f"(r.y) : "l"(v));
    return r;
}
__device__ __forceinline__ void ffma2(ull& d, ull a, ull b) {
    asm("fma.rn.f32x2 %0, %1, %2, %0;" : "+l"(d) : "l"(a), "l"(b));
}

__device__ __forceinline__ int ld_acq(const int* p) {
    int v;
    asm volatile("ld.acquire.gpu.b32 %0, [%1];" : "=r"(v) : "l"(p));
    return v;
}

__device__ __forceinline__ float sigm(float x) { return 1.0f / (1.0f + expf(-x)); }

__device__ __forceinline__ void cpasync16(uint32_t dst, const void* src) {
    asm volatile("cp.async.cg.shared.global [%0], [%1], 16;" :: "r"(dst), "l"(src) : "memory");
}
__device__ __forceinline__ void cp_commit() {
    asm volatile("cp.async.commit_group;" ::: "memory");
}
template<int N> __device__ __forceinline__ void cp_wait() {
    asm volatile("cp.async.wait_group %0;" :: "n"(N) : "memory");
}

// =====================================================================
// Kernel A: P[v, d*1024+g] = sum_e emb[v,e] * W{f,b}[e,g] + b{f,b}[g]
// (unchanged — measured 870us) Also resets group barrier counters.
// =====================================================================
__global__ void __launch_bounds__(256) proj_kernel(
    const float* __restrict__ emb,
    const float* __restrict__ Wf, const float* __restrict__ bf,
    const float* __restrict__ Wb, const float* __restrict__ bb)
{
    if (blockIdx.x == 0 && blockIdx.y == 0 && threadIdx.x < 16)
        g_ctr[threadIdx.x * 32] = 0;

    __shared__ ull   Ad[16][66];   // dup'd A; row stride 528 B (16B-aligned rows)
    __shared__ float Bs[16][64];

    const int tid = threadIdx.x;
    const int tx = tid & 15, ty = tid >> 4;
    const int m0 = ty * 4, n0 = tx * 4;
    const int vbase = blockIdx.y * 64;
    const int nbase = blockIdx.x * 64;
    const int d = nbase >> 10;
    const float* W    = d ? Wb : Wf;
    const float* bias = d ? bb : bf;
    const int gbase = nbase & 1023;

    ull acc[4][2] = {};

    for (int kt = 0; kt < 256; kt += 16) {
        #pragma unroll
        for (int i = tid; i < 1024; i += 256) {
            int row = i >> 4, k = i & 15;
            float v = emb[(size_t)(vbase + row) * EE + kt + k];
            Ad[k][row] = pack2(v, v);
        }
        #pragma unroll
        for (int i = tid; i < 1024; i += 256) {
            int k = i >> 6, c = i & 63;
            Bs[k][c] = W[(size_t)(kt + k) * G4H + gbase + c];
        }
        __syncthreads();
        #pragma unroll
        for (int k = 0; k < 16; k++) {
            ulonglong2 a01 = *(const ulonglong2*)&Ad[k][m0];
            ulonglong2 a23 = *(const ulonglong2*)&Ad[k][m0 + 2];
            ulonglong2 bb2 = *(const ulonglong2*)&Bs[k][n0];
            ffma2(acc[0][0], a01.x, bb2.x);
            ffma2(acc[0][1], a01.x, bb2.y);
            ffma2(acc[1][0], a01.y, bb2.x);
            ffma2(acc[1][1], a01.y, bb2.y);
            ffma2(acc[2][0], a23.x, bb2.x);
            ffma2(acc[2][1], a23.x, bb2.y);
            ffma2(acc[3][0], a23.y, bb2.x);
            ffma2(acc[3][1], a23.y, bb2.y);
        }
        __syncthreads();
    }

    #pragma unroll
    for (int i = 0; i < 4; i++) {
        int v = vbase + m0 + i;
        #pragma unroll
        for (int p = 0; p < 2; p++) {
            float2 va = unpack2(acc[i][p]);
            int c = n0 + 2 * p;
            va.x += bias[gbase + c];
            va.y += bias[gbase + c + 1];
            *(float2*)&g_P[(size_t)v * 2048 + nbase + c] = va;
        }
    }
}

// =====================================================================
// Kernel B: batch-partitioned bidirectional LSTM, crossbar-optimal layout.
//
// Group = (direction, 16-row batch block); 16 groups x 8 CTAs.
// CTA rank c owns h-cols [c*32, c*32+32). Thread (j = tid>>3, rp = tid&7):
// tile = hcol j x 4 gates x rows (2rp, 2rp+1); gates packed in f32x2 accums:
//   accA=(z_i,z_f)r0  accB=(z_g,z_o)r0  accC=(z_i,z_f)r1  accD=(z_g,z_o)r1
// SMEM: Up[k][j] = ulonglong2{(u_i,u_f),(u_g,u_o)}  (128 KB, non-dup)
//       hd[buf][k][row] = dup'd h pairs (2 x 32 KB)
// Inner loop per warp per k: 2 x LDS.128 (2 crossbar phases) + 4 FFMA2
//   -> 16 cyc/k per CTA: FMA floor = 4096 cyc/step.
// Producers publish h PRE-DUPLICATED (1 STG.128/thread) -> consumers
// cp.async 32 KB raw, zero transform. Tokens prefetched 1 step ahead.
// =====================================================================
#define UP_U2S   (256 * 32)                         // ulonglong2 count, 128 KB
#define HD_ULLS  (256 * 16)                         // per buffer, 32 KB
#define LSTM_SMEM_BYTES (UP_U2S * 16 + 2 * HD_ULLS * 8)   // 192 KB

__global__ void __launch_bounds__(256) lstm_kernel(
    const int* __restrict__ tokens,
    const float* __restrict__ Uf, const float* __restrict__ Ub)
{
    extern __shared__ char smraw[];
    ulonglong2* Up = (ulonglong2*)smraw;                  // [256 k][32 j]
    ull* hd = (ull*)(smraw + UP_U2S * 16);                // [2 buf][256 k][16 row]
    const uint32_t hd_addr = (uint32_t)__cvta_generic_to_shared(hd);

    const int tid = threadIdx.x;
    const int gr  = blockIdx.x >> 3;              // group 0..15
    const int c   = blockIdx.x & 7;               // rank in group
    const int d   = gr >> 3;                      // direction
    const int rb  = (gr & 7) * 16;                // batch row base
    const float* U = d ? Ub : Uf;

    const int j  = tid >> 3;                      // hcol within CTA (0..31)
    const int rp = tid & 7;                       // row pair (rows 2rp, 2rp+1)

    // Token dtype guard (jnp.int64 silently x32 in JAX unless x64 enabled).
    const bool is64 = ((tokens[1] | tokens[3] | tokens[5] | tokens[7]) == 0);
    const int ts = is64 ? 2 : 1;

    // Load U: Up[k][jj] = { (U[k][0*256+c*32+jj], U[k][1*256+...]),
    //                       (U[k][2*256+...],     U[k][3*256+...]) }
    // lanes jj-fastest -> coalesced 128B global reads per gate
    for (int i = tid; i < 8192; i += 256) {
        int k = i >> 5, jj = i & 31;
        const float* ub = U + (size_t)k * G4H + c * 32 + jj;
        ulonglong2 e;
        e.x = pack2(ub[0],   ub[256]);
        e.y = pack2(ub[512], ub[768]);
        Up[k * 32 + jj] = e;
    }
    // zero h buffer 0 (h(-1) = 0)
    for (int i = tid; i < HD_ULLS; i += 256) hd[i] = 0ull;
    __syncthreads();

    const int r0 = rb + 2 * rp;                   // global rows r0, r0+1
    const int* tokRow0 = tokens + (size_t)r0 * TT * ts;
    const int* tokRow1 = tokens + (size_t)(r0 + 1) * TT * ts;
    int* ctr = &g_ctr[gr * 32];

    // prefetch tokens for t = 0
    int te0 = d ? (TT - 1) : 0;
    int tokA = tokRow0[te0 * ts];
    int tokB = tokRow1[te0 * ts];

    float cs0 = 0.f, cs1 = 0.f;

    for (int t = 0; t < TT; t++) {
        const int buf = t & 1;

        int tA = (tokA >= 0 && tokA < VV) ? tokA : 0;
        int tB = (tokB >= 0 && tokB < VV) ? tokB : 0;

        // input-projection loads (consumed after k-loop; latency hidden)
        const float* PA = g_P + (size_t)tA * 2048 + d * 1024 + c * 32 + j;
        const float* PB = g_P + (size_t)tB * 2048 + d * 1024 + c * 32 + j;
        float pA0 = PA[0], pA1 = PA[256], pA2 = PA[512], pA3 = PA[768];
        float pB0 = PB[0], pB1 = PB[256], pB2 = PB[512], pB3 = PB[768];

        // prefetch tokens for t+1
        if (t + 1 < TT) {
            int te = d ? (TT - 2 - t) : (t + 1);
            tokA = tokRow0[te * ts];
            tokB = tokRow1[te * ts];
        }

        if (t > 0) { cp_wait<0>(); __syncthreads(); }   // h(t-1) staged

        // z = h(t-1) . U over k=256; per warp per k: 2 LDS.128 + 4 FFMA2
        const ulonglong2* up = Up + j;
        const ull* hb = hd + buf * HD_ULLS + 2 * rp;
        ull aA = 0, aB = 0, aC = 0, aD = 0;
        #pragma unroll 8
        for (int k = 0; k < HH; k++) {
            ulonglong2 u = up[k * 32];
            ulonglong2 hv = *(const ulonglong2*)(hb + k * 16);
            ffma2(aA, hv.x, u.x);
            ffma2(aB, hv.x, u.y);
            ffma2(aC, hv.y, u.x);
            ffma2(aD, hv.y, u.y);
        }

        float2 vA = unpack2(aA), vB = unpack2(aB);
        float2 vC = unpack2(aC), vD = unpack2(aD);
        float i0 = sigm(vA.x + pA0), f0 = sigm(vA.y + pA1);
        float g0 = tanhf(vB.x + pA2), o0 = sigm(vB.y + pA3);
        float i1 = sigm(vC.x + pB0), f1 = sigm(vC.y + pB1);
        float g1 = tanhf(vD.x + pB2), o1 = sigm(vD.y + pB3);
        cs0 = f0 * cs0 + i0 * g0;
        cs1 = f1 * cs1 + i1 * g1;
        float h0 = o0 * tanhf(cs0);
        float h1 = o1 * tanhf(cs1);

        if (t == TT - 1) {
            g_hfinT[d][c * 32 + j][r0]     = h0;
            g_hfinT[d][c * 32 + j][r0 + 1] = h1;
        } else {
            const int nb = buf ^ 1;
            // publish pre-duplicated h pairs: one aligned STG.128
            ulonglong2 outv;
            outv.x = pack2(h0, h0);
            outv.y = pack2(h1, h1);
            *(ulonglong2*)&g_hxd[gr][nb][c * 32 + j][2 * rp] = outv;
            __threadfence();
            __syncthreads();
            if (tid == 0) {
                atomicAdd(ctr, 1);
                const int target = 8 * (t + 1);
                while (ld_acq(ctr) < target) { }
            }
            __syncthreads();
            // stage full group h(t) (32 KB dup'd) into SMEM
            const ulonglong2* src = (const ulonglong2*)&g_hxd[gr][nb][0][0];
            const uint32_t dbase = hd_addr + (uint32_t)nb * (HD_ULLS * 8);
            #pragma unroll
            for (int q = 0; q < 8; q++) {
                int f = tid + q * 256;
                cpasync16(dbase + (uint32_t)f * 16, src + f);
            }
            cp_commit();
        }
    }
}

// =====================================================================
// Kernel C: head.  h1 = relu([hf|hb] @ W1 + b1); out = softmax(h1 @ W2 + b2)
// =====================================================================
__global__ void __launch_bounds__(256) head_kernel(
    const float* __restrict__ W1, const float* __restrict__ b1,
    const float* __restrict__ W2, const float* __restrict__ b2,
    float* __restrict__ out)
{
    __shared__ float hc[8][512];
    __shared__ float h1[8][256];

    const int tid = threadIdx.x;
    const int rb = blockIdx.x * 8;

    for (int i = tid; i < 4096; i += 256) {
        int rr = i >> 9, k = i & 511;
        int dd = k >> 8, kk = k & 255;
        hc[rr][k] = g_hfinT[dd][kk][rb + rr];
    }
    __syncthreads();

    const int jj = tid;
    float acc[8] = {0.f, 0.f, 0.f, 0.f, 0.f, 0.f, 0.f, 0.f};
    for (int k = 0; k < 512; k++) {
        float w = W1[(size_t)k * HH + jj];
        #pragma unroll
        for (int rr = 0; rr < 8; rr++) acc[rr] += hc[rr][k] * w;
    }
    float bj = b1[jj];
    #pragma unroll
    for (int rr = 0; rr < 8; rr++) h1[rr][jj] = fmaxf(acc[rr] + bj, 0.f);
    __syncthreads();

    const int rr = tid >> 5, cc = tid & 31;
    float l = b2[cc];
    for (int k = 0; k < HH; k++) l += h1[rr][k] * W2[(size_t)k * NC + cc];

    float m = l;
    #pragma unroll
    for (int o = 16; o > 0; o >>= 1) m = fmaxf(m, __shfl_xor_sync(0xffffffffu, m, o));
    float e = expf(l - m);
    float ssum = e;
    #pragma unroll
    for (int o = 16; o > 0; o >>= 1) ssum += __shfl_xor_sync(0xffffffffu, ssum, o);
    out[(size_t)(rb + rr) * NC + cc] = e / ssum;
}

// =====================================================================
extern "C" void kernel_launch(void* const* d_in, const int* in_sizes, int n_in,
                              void* d_out, int out_size)
{
    const int*   tokens = (const int*)d_in[0];
    const float* emb = (const float*)d_in[1];
    const float* Wf  = (const float*)d_in[2];
    const float* Uf  = (const float*)d_in[3];
    const float* bf  = (const float*)d_in[4];
    const float* Wb  = (const float*)d_in[5];
    const float* Ub  = (const float*)d_in[6];
    const float* bb  = (const float*)d_in[7];
    const float* W1  = (const float*)d_in[8];
    const float* b1  = (const float*)d_in[9];
    const float* W2  = (const float*)d_in[10];
    const float* b2  = (const float*)d_in[11];
    float* out = (float*)d_out;

    cudaFuncSetAttribute(lstm_kernel, cudaFuncAttributeMaxDynamicSharedMemorySize, LSTM_SMEM_BYTES);

    proj_kernel<<<dim3(32, 500), 256>>>(emb, Wf, bf, Wb, bb);
    lstm_kernel<<<128, 256, LSTM_SMEM_BYTES>>>(tokens, Uf, Ub);
    head_kernel<<<16, 256>>>(W1, b1, W2, b2, out);
}